// round 1
// baseline (speedup 1.0000x reference)
#include <cuda_runtime.h>
#include <cuda_bf16.h>
#include <cstdint>

// ============================================================================
// softassignment: out = intranorm( softmax(alpha * <x_b, zhat_bk>) @ zhat_b )
//   N=65536 rows, 16 books x 16 dims, K=256 codewords per book.
// Identities used (exact):
//   softmax(-a(1-dot)) == softmax(a*dot); softmax denominator cancels in the
//   final per-book L2 normalization, so it is never computed.
// Precision: 3-term split-bf16 MMAs (hi*hi + hi*lo + lo*hi) ~ 2^-16 operands.
// Exp on the FMA pipe (degree-5 poly), NOT MUFU (268M exps would take ~1.9ms).
// ============================================================================

#define NBOOK 16
#define DIMS  16
#define KCW   256
#define FDIM  256

// z1: [book][codeword][dim] (K-major rows), z2: [book][dim][codeword]
__device__ __nv_bfloat16 g_z1h[NBOOK * KCW * DIMS];
__device__ __nv_bfloat16 g_z1l[NBOOK * KCW * DIMS];
__device__ __nv_bfloat16 g_z2h[NBOOK * DIMS * KCW];
__device__ __nv_bfloat16 g_z2l[NBOOK * DIMS * KCW];

// ---------------------------------------------------------------------------
// Preprocess: intranorm the codebook, split to bf16 hi/lo, two layouts.
// grid = 16 books, block = 256 codewords.
// ---------------------------------------------------------------------------
__global__ void prep_z_kernel(const float* __restrict__ Zw) {
    int b  = blockIdx.x;
    int cw = threadIdx.x;
    const float* src = Zw + cw * FDIM + b * DIMS;
    float v[DIMS];
    float ss = 0.f;
#pragma unroll
    for (int d = 0; d < DIMS; d++) { v[d] = src[d]; ss = fmaf(v[d], v[d], ss); }
    // matches 1/clip(norm, 1e-12) exactly at the clip boundary
    float inv = rsqrtf(fmaxf(ss, 1e-24f));
#pragma unroll
    for (int d = 0; d < DIMS; d++) {
        float z = v[d] * inv;
        __nv_bfloat16 h = __float2bfloat16(z);
        float r = z - __bfloat162float(h);
        __nv_bfloat16 l = __float2bfloat16(r);
        int i1 = (b * KCW + cw) * DIMS + d;
        int i2 = (b * DIMS + d) * KCW + cw;
        g_z1h[i1] = h; g_z1l[i1] = l;
        g_z2h[i2] = h; g_z2l[i2] = l;
    }
}

// ---------------------------------------------------------------------------
// helpers
// ---------------------------------------------------------------------------
__device__ __forceinline__ void mma16816(float* c, const unsigned* a,
                                         unsigned b0, unsigned b1) {
    asm("mma.sync.aligned.m16n8k16.row.col.f32.bf16.bf16.f32 "
        "{%0,%1,%2,%3}, {%4,%5,%6,%7}, {%8,%9}, {%0,%1,%2,%3};"
        : "+f"(c[0]), "+f"(c[1]), "+f"(c[2]), "+f"(c[3])
        : "r"(a[0]), "r"(a[1]), "r"(a[2]), "r"(a[3]), "r"(b0), "r"(b1));
}

// pack (a,b) -> bf16x2 (a = low/even element), plus residual pack
__device__ __forceinline__ void splitpair(float a, float b,
                                          unsigned& hi, unsigned& lo) {
    unsigned h;
    asm("cvt.rn.bf16x2.f32 %0, %1, %2;" : "=r"(h) : "f"(b), "f"(a));
    float ha = __int_as_float(h << 16);
    float hb = __int_as_float(h & 0xFFFF0000u);
    float ra = a - ha;
    float rb = b - hb;
    unsigned l;
    asm("cvt.rn.bf16x2.f32 %0, %1, %2;" : "=r"(l) : "f"(rb), "f"(ra));
    hi = h; lo = l;
}

// fast 2^y on the FMA pipe. y <= ~0 (post max-subtract); rel err ~2.4e-6.
__device__ __forceinline__ float fexp2(float y) {
    y = fmaxf(y, -88.0f);
    float t = y + 12582912.0f;          // 1.5*2^23: RN gives rint(y) in mantissa
    float n = t - 12582912.0f;
    float f = y - n;                    // f in [-0.5, 0.5]
    float p = 1.3333558e-3f;            // ln2^5/120
    p = fmaf(p, f, 9.6181291e-3f);      // ln2^4/24
    p = fmaf(p, f, 5.5504109e-2f);      // ln2^3/6
    p = fmaf(p, f, 2.4022651e-1f);      // ln2^2/2
    p = fmaf(p, f, 6.9314718e-1f);      // ln2
    p = fmaf(p, f, 1.0f);
    int ib = __float_as_int(t);
    int sb = (ib - (0x4B400000 - 127)) << 23;   // 2^rint(y)
    return p * __int_as_float(sb);
}

#define L2E 1.4426950408889634f

// smem strides chosen for conflict-free B-fragment LDS:
//  z1 stride 24 elems (48B/row): bank = (12g+ti) mod 32 -> all distinct
//  z2 stride 264 elems (528B/row): bank = (4g+ti+8jk) mod 32 -> all distinct
#define S1STR 24
#define S2STR 264

// ---------------------------------------------------------------------------
// Main kernel: grid (N/128, 16 books), block 256 (8 warps x 16 rows).
// ---------------------------------------------------------------------------
__global__ void __launch_bounds__(256, 1)
soft_kernel(const float* __restrict__ feat, const float* __restrict__ alpha_p,
            float* __restrict__ out) {
    __shared__ __align__(16) __nv_bfloat16 s1h[KCW * S1STR];
    __shared__ __align__(16) __nv_bfloat16 s1l[KCW * S1STR];
    __shared__ __align__(16) __nv_bfloat16 s2h[DIMS * S2STR];
    __shared__ __align__(16) __nv_bfloat16 s2l[DIMS * S2STR];

    const int tid  = threadIdx.x;
    const int book = blockIdx.y;

    // ---- stage codebook (hi/lo, both layouts) into smem ----
    {
        // z1: one codeword (16 bf16 = 2 x uint4) per thread
        const uint4* p1h = (const uint4*)(g_z1h + book * (KCW * DIMS));
        const uint4* p1l = (const uint4*)(g_z1l + book * (KCW * DIMS));
        uint4 a0 = p1h[tid * 2], a1 = p1h[tid * 2 + 1];
        *(uint4*)&s1h[tid * S1STR]     = a0;
        *(uint4*)&s1h[tid * S1STR + 8] = a1;
        uint4 b0 = p1l[tid * 2], b1 = p1l[tid * 2 + 1];
        *(uint4*)&s1l[tid * S1STR]     = b0;
        *(uint4*)&s1l[tid * S1STR + 8] = b1;
        // z2: 16 rows x 32 uint4
        for (int i = tid; i < 512; i += 256) {
            int row = i >> 5, k = i & 31;
            ((uint4*)&s2h[row * S2STR])[k] =
                ((const uint4*)(g_z2h + book * (DIMS * KCW) + row * KCW))[k];
            ((uint4*)&s2l[row * S2STR])[k] =
                ((const uint4*)(g_z2l + book * (DIMS * KCW) + row * KCW))[k];
        }
    }
    __syncthreads();

    const float alpha = *alpha_p;
    const int w = tid >> 5, lane = tid & 31;
    const int g = lane >> 2, ti = lane & 3;

    const int row0 = blockIdx.x * 128 + w * 16 + g;    // rows row0, row0+8
    const float* x0 = feat + row0 * FDIM + book * DIMS;
    const float* x1 = x0 + 8 * FDIM;

    // A fragments of alpha*x (split bf16). m16n8k16 layout:
    //  a0:(r=g,   k=2ti..) a1:(r=g+8, k=2ti..) a2:(r=g, k=2ti+8..) a3:(r=g+8,+8)
    float2 xa = *(const float2*)(x0 + 2 * ti);
    float2 xb = *(const float2*)(x1 + 2 * ti);
    float2 xc = *(const float2*)(x0 + 2 * ti + 8);
    float2 xd = *(const float2*)(x1 + 2 * ti + 8);
    unsigned Ah[4], Al[4];
    splitpair(xa.x * alpha, xa.y * alpha, Ah[0], Al[0]);
    splitpair(xb.x * alpha, xb.y * alpha, Ah[1], Al[1]);
    splitpair(xc.x * alpha, xc.y * alpha, Ah[2], Al[2]);
    splitpair(xd.x * alpha, xd.y * alpha, Ah[3], Al[3]);

    // ---- GEMM1: logits[16 x 256] = (alpha x_b) . z_b^T, 3-way split ----
    float C[32][4];
#pragma unroll
    for (int j = 0; j < 32; j++) {
        C[j][0] = C[j][1] = C[j][2] = C[j][3] = 0.f;
        int cw = 8 * j + g;
        unsigned bh0 = *(const unsigned*)&s1h[cw * S1STR + 2 * ti];
        unsigned bh1 = *(const unsigned*)&s1h[cw * S1STR + 2 * ti + 8];
        unsigned bl0 = *(const unsigned*)&s1l[cw * S1STR + 2 * ti];
        unsigned bl1 = *(const unsigned*)&s1l[cw * S1STR + 2 * ti + 8];
        mma16816(C[j], Ah, bh0, bh1);
        mma16816(C[j], Ah, bl0, bl1);
        mma16816(C[j], Al, bh0, bh1);
    }

    // ---- row maxes (lanes sharing a row differ only in ti: xor 1, xor 2) ----
    float m0 = -1e30f, m1 = -1e30f;
#pragma unroll
    for (int j = 0; j < 32; j++) {
        m0 = fmaxf(m0, fmaxf(C[j][0], C[j][1]));
        m1 = fmaxf(m1, fmaxf(C[j][2], C[j][3]));
    }
    m0 = fmaxf(m0, __shfl_xor_sync(0xffffffffu, m0, 1));
    m0 = fmaxf(m0, __shfl_xor_sync(0xffffffffu, m0, 2));
    m1 = fmaxf(m1, __shfl_xor_sync(0xffffffffu, m1, 1));
    m1 = fmaxf(m1, __shfl_xor_sync(0xffffffffu, m1, 2));
    const float nm0 = -m0 * L2E;
    const float nm1 = -m1 * L2E;

    // ---- fused exp + GEMM2: D[16 x 16] = E . z_b (unnormalized softmax) ----
    // Accumulator layout of C == A-fragment layout of the recon MMA.
    float D0[4] = {0.f, 0.f, 0.f, 0.f};
    float D1[4] = {0.f, 0.f, 0.f, 0.f};
#pragma unroll
    for (int jk = 0; jk < 16; jk++) {
        float e00 = fexp2(fmaf(C[2 * jk][0],     L2E, nm0));
        float e01 = fexp2(fmaf(C[2 * jk][1],     L2E, nm0));
        float e02 = fexp2(fmaf(C[2 * jk][2],     L2E, nm1));
        float e03 = fexp2(fmaf(C[2 * jk][3],     L2E, nm1));
        float e10 = fexp2(fmaf(C[2 * jk + 1][0], L2E, nm0));
        float e11 = fexp2(fmaf(C[2 * jk + 1][1], L2E, nm0));
        float e12 = fexp2(fmaf(C[2 * jk + 1][2], L2E, nm1));
        float e13 = fexp2(fmaf(C[2 * jk + 1][3], L2E, nm1));
        unsigned Eh[4], El[4];
        splitpair(e00, e01, Eh[0], El[0]);   // r=g,   k=2ti..
        splitpair(e02, e03, Eh[1], El[1]);   // r=g+8, k=2ti..
        splitpair(e10, e11, Eh[2], El[2]);   // r=g,   k=2ti+8..
        splitpair(e12, e13, Eh[3], El[3]);   // r=g+8, k=2ti+8..

        int kb = 16 * jk + 2 * ti;
        unsigned b0h = *(const unsigned*)&s2h[g * S2STR + kb];
        unsigned b1h = *(const unsigned*)&s2h[g * S2STR + kb + 8];
        unsigned b0l = *(const unsigned*)&s2l[g * S2STR + kb];
        unsigned b1l = *(const unsigned*)&s2l[g * S2STR + kb + 8];
        unsigned c0h = *(const unsigned*)&s2h[(g + 8) * S2STR + kb];
        unsigned c1h = *(const unsigned*)&s2h[(g + 8) * S2STR + kb + 8];
        unsigned c0l = *(const unsigned*)&s2l[(g + 8) * S2STR + kb];
        unsigned c1l = *(const unsigned*)&s2l[(g + 8) * S2STR + kb + 8];

        mma16816(D0, Eh, b0h, b1h);
        mma16816(D0, Eh, b0l, b1l);
        mma16816(D0, El, b0h, b1h);
        mma16816(D1, Eh, c0h, c1h);
        mma16816(D1, Eh, c0l, c1l);
        mma16816(D1, El, c0h, c1h);
    }

    // ---- per-row L2 normalize over the 16 dims (softmax denom cancels) ----
    float ss0 = D0[0] * D0[0] + D0[1] * D0[1] + D1[0] * D1[0] + D1[1] * D1[1];
    float ss1 = D0[2] * D0[2] + D0[3] * D0[3] + D1[2] * D1[2] + D1[3] * D1[3];
    ss0 += __shfl_xor_sync(0xffffffffu, ss0, 1);
    ss0 += __shfl_xor_sync(0xffffffffu, ss0, 2);
    ss1 += __shfl_xor_sync(0xffffffffu, ss1, 1);
    ss1 += __shfl_xor_sync(0xffffffffu, ss1, 2);
    float inv0 = rsqrtf(fmaxf(ss0, 1e-24f));
    float inv1 = rsqrtf(fmaxf(ss1, 1e-24f));

    float* o0 = out + row0 * FDIM + book * DIMS;
    float* o1 = o0 + 8 * FDIM;
    *(float2*)(o0 + 2 * ti)     = make_float2(D0[0] * inv0, D0[1] * inv0);
    *(float2*)(o0 + 2 * ti + 8) = make_float2(D1[0] * inv0, D1[1] * inv0);
    *(float2*)(o1 + 2 * ti)     = make_float2(D0[2] * inv1, D0[3] * inv1);
    *(float2*)(o1 + 2 * ti + 8) = make_float2(D1[2] * inv1, D1[3] * inv1);
}

// ---------------------------------------------------------------------------
extern "C" void kernel_launch(void* const* d_in, const int* in_sizes, int n_in,
                              void* d_out, int out_size) {
    const float* feat    = (const float*)d_in[0];
    const float* Zw      = (const float*)d_in[1];
    const float* alpha_p = (const float*)d_in[3];   // d_in[2] = n_book (unused)
    float* out = (float*)d_out;
    int N = in_sizes[0] / FDIM;

    prep_z_kernel<<<NBOOK, KCW>>>(Zw);
    soft_kernel<<<dim3(N / 128, NBOOK), 256>>>(feat, alpha_p, out);
}

// round 2
// speedup vs baseline: 1.7456x; 1.7456x over previous
#include <cuda_runtime.h>
#include <cuda_bf16.h>
#include <cstdint>

// ============================================================================
// softassignment on B200 (sm_100a), round 2.
//   out = intranorm( softmax(alpha*<x_b, zhat_bk>) @ zhat_b ), exact identities:
//   - softmax(-a(1-dot)) == softmax(a*dot)
//   - softmax denominator cancels in final per-book L2 norm (never computed)
//   - row-max replaced by Cauchy-Schwarz bound M = a*L2E*||x_b|| - 50:
//     y = a*L2E*dot - M <= 50 always -> no overflow; underflow flushes to 0.
//     This removes the GEMM1->max dependency and enables K-chunking (regs!).
// Precision: 3-term split-bf16 MMAs (hi*hi + hi*lo + lo*hi), deg-4 exp poly.
// Exp/split on packed f32x2 FMA pipe (sm_100+), never MUFU.
// ============================================================================

#define NBOOK 16
#define DIMS  16
#define KCW   256
#define FDIM  256
#define L2E   1.4426950408889634f

typedef unsigned long long u64;

// Packed codebook, layouts match the MMA fragment needs exactly (one LDS.128
// yields bh0,bh1,bl0,bl1):
//  g_p1: [book][cw][ti]  16B = {h[2ti],h[2ti+1],h[2ti+8],h[2ti+9], l[same]}
//  g_p2: [book][d][m][ti]16B = same pattern over cw = 16m + {2ti,2ti+1,2ti+8,2ti+9}
__device__ uint4 g_p1[NBOOK * KCW * 4];
__device__ uint4 g_p2[NBOOK * DIMS * 64];

// ---------------------------------------------------------------------------
__global__ void prep_z_kernel(const float* __restrict__ Zw) {
    int b = blockIdx.x, cw = threadIdx.x;
    const float* src = Zw + cw * FDIM + b * DIMS;
    float v[DIMS], ss = 0.f;
#pragma unroll
    for (int d = 0; d < DIMS; d++) { v[d] = src[d]; ss = fmaf(v[d], v[d], ss); }
    float inv = rsqrtf(fmaxf(ss, 1e-24f));   // == 1/clip(norm,1e-12)
    __nv_bfloat16 h[DIMS], l[DIMS];
#pragma unroll
    for (int d = 0; d < DIMS; d++) {
        float z = v[d] * inv;
        h[d] = __float2bfloat16(z);
        l[d] = __float2bfloat16(z - __bfloat162float(h[d]));
    }
    __nv_bfloat16* p1 = (__nv_bfloat16*)(g_p1 + (b * KCW + cw) * 4);
#pragma unroll
    for (int ti = 0; ti < 4; ti++) {
        p1[ti * 8 + 0] = h[2 * ti];     p1[ti * 8 + 1] = h[2 * ti + 1];
        p1[ti * 8 + 2] = h[2 * ti + 8]; p1[ti * 8 + 3] = h[2 * ti + 9];
        p1[ti * 8 + 4] = l[2 * ti];     p1[ti * 8 + 5] = l[2 * ti + 1];
        p1[ti * 8 + 6] = l[2 * ti + 8]; p1[ti * 8 + 7] = l[2 * ti + 9];
    }
    int m = cw >> 4, r = cw & 15;
    int tj = (r >> 1) & 3;
    int slot = (r & 1) + ((r >> 3) << 1);
#pragma unroll
    for (int d = 0; d < DIMS; d++) {
        __nv_bfloat16* q = (__nv_bfloat16*)(g_p2 + ((b * DIMS + d) * 16 + m) * 4 + tj);
        q[slot] = h[d];
        q[slot + 4] = l[d];
    }
}

// ------------------------- packed f32x2 helpers ----------------------------
__device__ __forceinline__ u64 pk2(float lo, float hi) {
    u64 r; asm("mov.b64 %0, {%1,%2};" : "=l"(r) : "f"(lo), "f"(hi)); return r;
}
__device__ __forceinline__ void u2f(u64 v, float& lo, float& hi) {
    asm("mov.b64 {%0,%1}, %2;" : "=f"(lo), "=f"(hi) : "l"(v));
}
__device__ __forceinline__ u64 fma2(u64 a, u64 b, u64 c) {
    u64 d; asm("fma.rn.f32x2 %0, %1, %2, %3;" : "=l"(d) : "l"(a), "l"(b), "l"(c)); return d;
}
__device__ __forceinline__ u64 add2(u64 a, u64 b) {
    u64 d; asm("add.rn.f32x2 %0, %1, %2;" : "=l"(d) : "l"(a), "l"(b)); return d;
}
__device__ __forceinline__ u64 mul2(u64 a, u64 b) {
    u64 d; asm("mul.rn.f32x2 %0, %1, %2;" : "=l"(d) : "l"(a), "l"(b)); return d;
}

__device__ __forceinline__ void mma16816(float* c, const unsigned* a,
                                         unsigned b0, unsigned b1) {
    asm("mma.sync.aligned.m16n8k16.row.col.f32.bf16.bf16.f32 "
        "{%0,%1,%2,%3}, {%4,%5,%6,%7}, {%8,%9}, {%0,%1,%2,%3};"
        : "+f"(c[0]), "+f"(c[1]), "+f"(c[2]), "+f"(c[3])
        : "r"(a[0]), "r"(a[1]), "r"(a[2]), "r"(a[3]), "r"(b0), "r"(b1));
}
__device__ __forceinline__ void mma16816z(float* d, const unsigned* a,
                                          unsigned b0, unsigned b1) {
    asm("mma.sync.aligned.m16n8k16.row.col.f32.bf16.bf16.f32 "
        "{%0,%1,%2,%3}, {%4,%5,%6,%7}, {%8,%9}, {%10,%10,%10,%10};"
        : "=f"(d[0]), "=f"(d[1]), "=f"(d[2]), "=f"(d[3])
        : "r"(a[0]), "r"(a[1]), "r"(a[2]), "r"(a[3]), "r"(b0), "r"(b1), "f"(0.f));
}

// scalar splitpair (prologue only)
__device__ __forceinline__ void splitpair(float a, float b, unsigned& hi, unsigned& lo) {
    unsigned h;
    asm("cvt.rn.bf16x2.f32 %0, %1, %2;" : "=r"(h) : "f"(b), "f"(a));
    float ra = a - __int_as_float(h << 16);
    float rb = b - __int_as_float(h & 0xFFFF0000u);
    unsigned l;
    asm("cvt.rn.bf16x2.f32 %0, %1, %2;" : "=r"(l) : "f"(rb), "f"(ra));
    hi = h; lo = l;
}

// packed exp2 of pair: e = 2^(c*L2E + off). off chosen so arg <= 50 always;
// args < -126 flush to 0 via int-side clamp (no FMNMX on the float path).
#define EXPP(RES, c0, c1, OFF) do {                                          \
    u64 _y = fma2(pk2((c0), (c1)), K_L2E, (OFF));                            \
    u64 _t = add2(_y, K_BIG);                                                \
    u64 _n = add2(_t, K_NBIG);                                               \
    u64 _f = fma2(_n, K_M1, _y);                                             \
    u64 _p = fma2(K_C4, _f, K_C3);                                           \
    _p = fma2(_p, _f, K_C2);                                                 \
    _p = fma2(_p, _f, K_C1);                                                 \
    _p = fma2(_p, _f, K_ONE);                                                \
    unsigned _i0 = (unsigned)_t, _i1 = (unsigned)(_t >> 32);                 \
    int _e0 = (int)(_i0 - 0x4B3FFF81u); _e0 = _e0 < 0 ? 0 : _e0;             \
    int _e1 = (int)(_i1 - 0x4B3FFF81u); _e1 = _e1 < 0 ? 0 : _e1;             \
    u64 _s = pk2(__int_as_float(_e0 << 23), __int_as_float(_e1 << 23));      \
    RES = mul2(_p, _s);                                                      \
} while (0)

// packed split of an exp pair into bf16x2 hi + bf16x2 lo fragments
#define SPLITP(H, L, E) do {                                                 \
    float _a, _b; u2f((E), _a, _b);                                          \
    unsigned _h;                                                             \
    asm("cvt.rn.bf16x2.f32 %0, %1, %2;" : "=r"(_h) : "f"(_b), "f"(_a));      \
    u64 _hv = pk2(__int_as_float(_h << 16), __int_as_float(_h & 0xFFFF0000u)); \
    u64 _r = fma2(_hv, K_M1, (E));                                           \
    float _ra, _rb; u2f(_r, _ra, _rb);                                       \
    unsigned _l;                                                             \
    asm("cvt.rn.bf16x2.f32 %0, %1, %2;" : "=r"(_l) : "f"(_rb), "f"(_ra));    \
    H = _h; L = _l;                                                          \
} while (0)

// ---------------------------------------------------------------------------
// Main kernel: grid (N/128, 16 books), block 256 (8 warps x 16 rows), 2 CTA/SM.
// ---------------------------------------------------------------------------
__global__ void __launch_bounds__(256, 2)
soft_kernel(const float* __restrict__ feat, const float* __restrict__ alpha_p,
            float* __restrict__ out) {
    __shared__ uint4 s1[KCW * 4];        // 16 KB, stride 64B (conflict-free)
    __shared__ uint4 s2[DIMS * 68];      // 17.4 KB, d-stride 1088B (conflict-free)

    const int tid = threadIdx.x;
    const int book = blockIdx.y;

    {
        const uint4* p1 = g_p1 + book * (KCW * 4);
        const uint4* p2 = g_p2 + book * (DIMS * 64);
#pragma unroll
        for (int i = tid; i < 1024; i += 256) s1[i] = p1[i];
#pragma unroll
        for (int i = tid; i < 1024; i += 256) {
            int d = i >> 6, o = i & 63;
            s2[d * 68 + o] = p2[i];
        }
    }
    __syncthreads();

    const float alpha = *alpha_p;
    const int w = tid >> 5, lane = tid & 31;
    const int g = lane >> 2, ti = lane & 3;

    const int row0 = blockIdx.x * 128 + w * 16 + g;      // rows row0, row0+8
    const float* x0 = feat + row0 * FDIM + book * DIMS;
    const float* x1 = x0 + 8 * FDIM;

    // A fragments of alpha*x (split bf16), m16n8k16 layout
    float2 xa = *(const float2*)(x0 + 2 * ti);
    float2 xb = *(const float2*)(x1 + 2 * ti);
    float2 xc = *(const float2*)(x0 + 2 * ti + 8);
    float2 xd = *(const float2*)(x1 + 2 * ti + 8);
    unsigned Ah[4], Al[4];
    splitpair(xa.x * alpha, xa.y * alpha, Ah[0], Al[0]);
    splitpair(xb.x * alpha, xb.y * alpha, Ah[1], Al[1]);
    splitpair(xc.x * alpha, xc.y * alpha, Ah[2], Al[2]);
    splitpair(xd.x * alpha, xd.y * alpha, Ah[3], Al[3]);

    // Cauchy-Schwarz max proxy: off = 50 - alpha*L2E*||x_row||
    float sg0 = xa.x * xa.x + xa.y * xa.y + xc.x * xc.x + xc.y * xc.y;
    float sg1 = xb.x * xb.x + xb.y * xb.y + xd.x * xd.x + xd.y * xd.y;
    sg0 += __shfl_xor_sync(0xffffffffu, sg0, 1);
    sg0 += __shfl_xor_sync(0xffffffffu, sg0, 2);
    sg1 += __shfl_xor_sync(0xffffffffu, sg1, 1);
    sg1 += __shfl_xor_sync(0xffffffffu, sg1, 2);
    float of0 = 50.f - alpha * L2E * sqrtf(sg0);
    float of1 = 50.f - alpha * L2E * sqrtf(sg1);
    const u64 OFF0 = pk2(of0, of0);
    const u64 OFF1 = pk2(of1, of1);

    // packed constants
    const u64 K_L2E  = pk2(L2E, L2E);
    const u64 K_BIG  = pk2(12582912.f, 12582912.f);
    const u64 K_NBIG = pk2(-12582912.f, -12582912.f);
    const u64 K_M1   = pk2(-1.f, -1.f);
    const u64 K_C4   = pk2(9.6181291e-3f, 9.6181291e-3f);
    const u64 K_C3   = pk2(5.5504109e-2f, 5.5504109e-2f);
    const u64 K_C2   = pk2(2.4022651e-1f, 2.4022651e-1f);
    const u64 K_C1   = pk2(6.9314718e-1f, 6.9314718e-1f);
    const u64 K_ONE  = pk2(1.f, 1.f);

    float D0[4] = {0.f, 0.f, 0.f, 0.f};
    float D1[4] = {0.f, 0.f, 0.f, 0.f};

    const uint4* b1base = s1 + g * 4 + ti;           // + cw*4
    const uint4* b2g    = s2 + g * 68 + ti;          // + m*4
    const uint4* b2g8   = s2 + (g + 8) * 68 + ti;

#pragma unroll 1
    for (int c = 0; c < 4; c++) {
        // ---- GEMM1 chunk: logits C[8][4] for codewords 64c .. 64c+63 ----
        float C[8][4];
#pragma unroll
        for (int j = 0; j < 8; j++) {
            uint4 B = b1base[(c * 64 + 8 * j) * 4];
            mma16816z(C[j], Ah, B.x, B.y);   // hi*hi (zero-init)
            mma16816 (C[j], Ah, B.z, B.w);   // hi*lo
            mma16816 (C[j], Al, B.x, B.y);   // lo*hi
        }
        // ---- fused exp + GEMM2 accumulate ----
#pragma unroll
        for (int m = 0; m < 4; m++) {
            int mg = c * 4 + m;
            uint4 Bg  = b2g[mg * 4];
            uint4 Bh8 = b2g8[mg * 4];
            u64 E0, E1, E2, E3;
            EXPP(E0, C[2 * m][0],     C[2 * m][1],     OFF0);
            EXPP(E1, C[2 * m][2],     C[2 * m][3],     OFF1);
            EXPP(E2, C[2 * m + 1][0], C[2 * m + 1][1], OFF0);
            EXPP(E3, C[2 * m + 1][2], C[2 * m + 1][3], OFF1);
            unsigned Eh[4], El[4];
            SPLITP(Eh[0], El[0], E0);
            SPLITP(Eh[1], El[1], E1);
            SPLITP(Eh[2], El[2], E2);
            SPLITP(Eh[3], El[3], E3);
            mma16816(D0, Eh, Bg.x, Bg.y);    // h*h
            mma16816(D0, Eh, Bg.z, Bg.w);    // h*l
            mma16816(D0, El, Bg.x, Bg.y);    // l*h
            mma16816(D1, Eh, Bh8.x, Bh8.y);
            mma16816(D1, Eh, Bh8.z, Bh8.w);
            mma16816(D1, El, Bh8.x, Bh8.y);
        }
    }

    // ---- per-row L2 normalize over 16 dims (softmax denom cancels) ----
    float ss0 = D0[0] * D0[0] + D0[1] * D0[1] + D1[0] * D1[0] + D1[1] * D1[1];
    float ss1 = D0[2] * D0[2] + D0[3] * D0[3] + D1[2] * D1[2] + D1[3] * D1[3];
    ss0 += __shfl_xor_sync(0xffffffffu, ss0, 1);
    ss0 += __shfl_xor_sync(0xffffffffu, ss0, 2);
    ss1 += __shfl_xor_sync(0xffffffffu, ss1, 1);
    ss1 += __shfl_xor_sync(0xffffffffu, ss1, 2);
    float inv0 = rsqrtf(fmaxf(ss0, 1e-24f));
    float inv1 = rsqrtf(fmaxf(ss1, 1e-24f));

    float* o0 = out + row0 * FDIM + book * DIMS;
    float* o1 = o0 + 8 * FDIM;
    *(float2*)(o0 + 2 * ti)     = make_float2(D0[0] * inv0, D0[1] * inv0);
    *(float2*)(o0 + 2 * ti + 8) = make_float2(D1[0] * inv0, D1[1] * inv0);
    *(float2*)(o1 + 2 * ti)     = make_float2(D0[2] * inv1, D0[3] * inv1);
    *(float2*)(o1 + 2 * ti + 8) = make_float2(D1[2] * inv1, D1[3] * inv1);
}

// ---------------------------------------------------------------------------
extern "C" void kernel_launch(void* const* d_in, const int* in_sizes, int n_in,
                              void* d_out, int out_size) {
    const float* feat    = (const float*)d_in[0];
    const float* Zw      = (const float*)d_in[1];
    const float* alpha_p = (const float*)d_in[3];   // d_in[2] = n_book (unused)
    float* out = (float*)d_out;
    int N = in_sizes[0] / FDIM;

    prep_z_kernel<<<NBOOK, KCW>>>(Zw);
    soft_kernel<<<dim3(N / 128, NBOOK), 256>>>(feat, alpha_p, out);
}